// round 13
// baseline (speedup 1.0000x reference)
#include <cuda_runtime.h>
#include <cstdint>

#define BB 8
#define CC 64
#define HH 256
#define WW 256
#define PLANE (HH*WW)
#define EPSN 1e-5f
#define SLOPE 0.01f
#define NOFF 169
#define CROP 244
#define NCROP (CROP*CROP)

__device__ __forceinline__ uint32_t pack2bf(float lo, float hi) {
    uint32_t r;
    asm("cvt.rn.bf16x2.f32 %0, %1, %2;" : "=r"(r) : "f"(hi), "f"(lo));
    return r;
}
// D += A(16x16 bf16) * B(16x8 bf16), f32 accum. Canonical sm_80 fragments.
__device__ __forceinline__ void mma16816(float* d, const uint32_t* a,
                                         uint32_t b0, uint32_t b1) {
    asm volatile("mma.sync.aligned.m16n8k16.row.col.f32.bf16.bf16.f32 "
        "{%0,%1,%2,%3}, {%4,%5,%6,%7}, {%8,%9}, {%0,%1,%2,%3};"
        : "+f"(d[0]), "+f"(d[1]), "+f"(d[2]), "+f"(d[3])
        : "r"(a[0]), "r"(a[1]), "r"(a[2]), "r"(a[3]), "r"(b0), "r"(b1));
}

// ---------------- scratch ----------------
__device__ float g_bufA[BB*CC*PLANE];
__device__ float g_bufB[BB*CC*PLANE];
__device__ float g_stats[8*BB*CC*2];
__device__ float g_hr[BB*PLANE];
__device__ float g_loss[NOFF*BB];
__device__ uint32_t g_wpack[7*9*2*2048];   // [l][tap][split][oc][icpair]

__global__ void zero_stats_kernel() {
    int i = blockIdx.x * blockDim.x + threadIdx.x;
    if (i < 8*BB*CC*2) g_stats[i] = 0.f;
}

// Pack trunk weights to bf16 hi/lo pairs: wpack[l][tap][sp][oc][icp]
__global__ void wprep_kernel(const float* __restrict__ ws) {
    int idx = blockIdx.x*256 + threadIdx.x;
    if (idx >= 7*9*2*2048) return;
    int icp = idx & 31, oc = (idx >> 5) & 63;
    int rest = idx >> 11;
    int sp = rest & 1; rest >>= 1;
    int tap = rest % 9, l = rest / 9;
    float w0 = ws[(((size_t)l*64 + oc)*64 + icp*2    )*9 + tap];
    float w1 = ws[(((size_t)l*64 + oc)*64 + icp*2 + 1)*9 + tap];
    uint32_t hp = pack2bf(w0, w1), v;
    if (sp == 0) v = hp;
    else v = pack2bf(w0 - __uint_as_float(hp << 16), w1 - __uint_as_float(hp & 0xFFFF0000u));
    g_wpack[idx] = v;
}

// ---------------- layer 0: 1->64, per-pixel ----------------
__global__ void __launch_bounds__(256) conv0_kernel(
    const float* __restrict__ in, const float* __restrict__ w0, float* __restrict__ out) {
    __shared__ float w[576];
    int y = blockIdx.x, b = blockIdx.y, x = threadIdx.x;
    for (int i = threadIdx.x; i < 576; i += 256) w[i] = w0[i];
    int ym = max(y-1, 0), yp = min(y+1, HH-1);
    int xm = max(x-1, 0), xp = min(x+1, WW-1);
    const float* ip = in + (size_t)b*PLANE;
    float p[9] = { ip[ym*WW+xm], ip[ym*WW+x], ip[ym*WW+xp],
                   ip[y *WW+xm], ip[y *WW+x], ip[y *WW+xp],
                   ip[yp*WW+xm], ip[yp*WW+x], ip[yp*WW+xp] };
    __syncthreads();
    for (int oc = 0; oc < 64; oc++) {
        float a = 0.f;
        #pragma unroll
        for (int k = 0; k < 9; k++) a = fmaf(p[k], w[oc*9+k], a);
        out[(size_t)(b*CC + oc)*PLANE + y*WW + x] = a;
    }
}

// per-channel (sum, sumsq); one block per (b,c)
__global__ void __launch_bounds__(256) stats_kernel(
    const float* __restrict__ buf, float* __restrict__ st) {
    int ch = blockIdx.x;
    const float4* p = (const float4*)(buf + (size_t)ch*PLANE);
    float s = 0.f, s2 = 0.f;
    for (int i = threadIdx.x; i < PLANE/4; i += 256) {
        float4 v = p[i];
        s += v.x + v.y + v.z + v.w;
        s2 = fmaf(v.x, v.x, fmaf(v.y, v.y, fmaf(v.z, v.z, fmaf(v.w, v.w, s2))));
    }
    __shared__ float sh[2][8];
    int lane = threadIdx.x & 31, w = threadIdx.x >> 5;
    #pragma unroll
    for (int d = 16; d > 0; d >>= 1) {
        s  += __shfl_down_sync(~0u, s, d);
        s2 += __shfl_down_sync(~0u, s2, d);
    }
    if (lane == 0) { sh[0][w] = s; sh[1][w] = s2; }
    __syncthreads();
    if (threadIdx.x == 0) {
        float S = 0.f, S2 = 0.f;
        #pragma unroll
        for (int i = 0; i < 8; i++) { S += sh[0][i]; S2 += sh[1][i]; }
        st[ch*2] = S; st[ch*2+1] = S2;
    }
}

// ---------------- mma.sync 64->64 conv layer ----------------
// CTA = (128px half-row x0, output row y, batch b). M=128 (8 warps x m16),
// N=64 oc, K=576. Input staged normed+lrelu as bf16 hi/lo pairs, pitch 36 u32
// (banks: 4g+tig -> conflict-free fragment loads). Weights per tap from g_wpack.
#define PITCH 36
#define AH_OFF 0
#define AL_OFF 14040
#define WH_OFF 28080
#define WL_OFF 30384
#define RS_OFF 32688
#define NM_OFF 32752
#define TSM    (32816*4)

__global__ void __launch_bounds__(256, 1) tconv_kernel(
    const float* __restrict__ in, const float* __restrict__ stats_in,
    float* __restrict__ out, float* __restrict__ stats_out, int l) {
    extern __shared__ uint32_t sm[];
    float* smf = (float*)sm;
    const int t = threadIdx.x, wid = t >> 5, lane = t & 31;
    const int g = lane >> 2, tig = lane & 3;
    const int x0 = blockIdx.x * 128, y = blockIdx.y, b = blockIdx.z;

    if (t < 64) {
        float2 st = *(const float2*)&stats_in[(b*CC + t)*2];
        float m = st.x * (1.f/65536.f);
        float r = rsqrtf(fmaxf(st.y * (1.f/65536.f) - m*m, 0.f) + EPSN);
        smf[RS_OFF + t] = r; smf[NM_OFF + t] = -m*r;
    }
    __syncthreads();

    // stage input: 3 rows x 130 px x 32 ic-pairs, hi/lo
    for (int idx = t; idx < 3*130*32; idx += 256) {
        int icp = idx / 390, rem = idx - icp*390;
        int r = rem / 130, px = rem - r*130;
        int gy = min(max(y + r - 1, 0), HH-1);
        int gx = min(max(x0 + px - 1, 0), WW-1);
        int ic = icp*2;
        float v0 = in[(size_t)(b*CC + ic    )*PLANE + gy*WW + gx];
        float v1 = in[(size_t)(b*CC + ic + 1)*PLANE + gy*WW + gx];
        v0 = fmaf(v0, smf[RS_OFF+ic],   smf[NM_OFF+ic]);   v0 = (v0 >= 0.f) ? v0 : SLOPE*v0;
        v1 = fmaf(v1, smf[RS_OFF+ic+1], smf[NM_OFF+ic+1]); v1 = (v1 >= 0.f) ? v1 : SLOPE*v1;
        uint32_t hp = pack2bf(v0, v1);
        uint32_t lp = pack2bf(v0 - __uint_as_float(hp << 16),
                              v1 - __uint_as_float(hp & 0xFFFF0000u));
        int off = (r*130 + px)*PITCH + icp;
        sm[AH_OFF + off] = hp;
        sm[AL_OFF + off] = lp;
    }

    float d[8][4];
    #pragma unroll
    for (int nt = 0; nt < 8; nt++)
        #pragma unroll
        for (int i = 0; i < 4; i++) d[nt][i] = 0.f;

    for (int tap = 0; tap < 9; tap++) {
        __syncthreads();
        const uint32_t* wh = g_wpack + (((size_t)l*9 + tap)*2    )*2048;
        const uint32_t* wl = g_wpack + (((size_t)l*9 + tap)*2 + 1)*2048;
        for (int i = t; i < 2048; i += 256) {
            int oc = i >> 5, icp = i & 31;
            sm[WH_OFF + oc*PITCH + icp] = wh[i];
            sm[WL_OFF + oc*PITCH + icp] = wl[i];
        }
        __syncthreads();
        int kr = tap / 3, kc = tap - kr*3;
        int pxb = wid*16 + kc;                 // includes the -1 pad shift
        #pragma unroll
        for (int q = 0; q < 4; q++) {
            int base = (kr*130 + pxb)*PITCH + q*8;
            uint32_t ah[4], al[4];
            ah[0] = sm[AH_OFF + base + g*PITCH + tig];
            ah[1] = sm[AH_OFF + base + (g+8)*PITCH + tig];
            ah[2] = sm[AH_OFF + base + g*PITCH + 4 + tig];
            ah[3] = sm[AH_OFF + base + (g+8)*PITCH + 4 + tig];
            al[0] = sm[AL_OFF + base + g*PITCH + tig];
            al[1] = sm[AL_OFF + base + (g+8)*PITCH + tig];
            al[2] = sm[AL_OFF + base + g*PITCH + 4 + tig];
            al[3] = sm[AL_OFF + base + (g+8)*PITCH + 4 + tig];
            #pragma unroll
            for (int nt = 0; nt < 8; nt++) {
                int n = nt*8 + g;
                uint32_t bh0 = sm[WH_OFF + n*PITCH + q*8 + tig];
                uint32_t bh1 = sm[WH_OFF + n*PITCH + q*8 + 4 + tig];
                uint32_t bl0 = sm[WL_OFF + n*PITCH + q*8 + tig];
                uint32_t bl1 = sm[WL_OFF + n*PITCH + q*8 + 4 + tig];
                mma16816(d[nt], ah, bh0, bh1);   // hh
                mma16816(d[nt], ah, bl0, bl1);   // hl
                mma16816(d[nt], al, bh0, bh1);   // lh
            }
        }
    }

    // write out + per-oc stats. D frag: d0=(px g, oc tig*2) d1=(g, +1)
    // d2=(g+8, tig*2) d3=(g+8, +1)
    int px0 = x0 + wid*16 + g, px1 = px0 + 8;
    #pragma unroll
    for (int nt = 0; nt < 8; nt++) {
        int oc0 = nt*8 + tig*2, oc1 = oc0 + 1;
        out[(size_t)(b*CC + oc0)*PLANE + y*WW + px0] = d[nt][0];
        out[(size_t)(b*CC + oc1)*PLANE + y*WW + px0] = d[nt][1];
        out[(size_t)(b*CC + oc0)*PLANE + y*WW + px1] = d[nt][2];
        out[(size_t)(b*CC + oc1)*PLANE + y*WW + px1] = d[nt][3];
        float s0 = d[nt][0] + d[nt][2], q0 = d[nt][0]*d[nt][0] + d[nt][2]*d[nt][2];
        float s1 = d[nt][1] + d[nt][3], q1 = d[nt][1]*d[nt][1] + d[nt][3]*d[nt][3];
        #pragma unroll
        for (int m = 4; m <= 16; m <<= 1) {       // reduce over g bits
            s0 += __shfl_xor_sync(~0u, s0, m);
            q0 += __shfl_xor_sync(~0u, q0, m);
            s1 += __shfl_xor_sync(~0u, s1, m);
            q1 += __shfl_xor_sync(~0u, q1, m);
        }
        if (g == 0) {
            atomicAdd(&stats_out[(b*CC + oc0)*2 + 0], s0);
            atomicAdd(&stats_out[(b*CC + oc0)*2 + 1], q0);
            atomicAdd(&stats_out[(b*CC + oc1)*2 + 0], s1);
            atomicAdd(&stats_out[(b*CC + oc1)*2 + 1], q1);
        }
    }
}

// ---------------- projection 64->1, per-pixel ----------------
__global__ void __launch_bounds__(256) proj_kernel(
    const float* __restrict__ in, const float* __restrict__ st,
    const float* __restrict__ wp, const float* __restrict__ bp,
    const float* __restrict__ xIn, float* __restrict__ hr,
    float* __restrict__ dout, int write_dout) {
    __shared__ float w[576], rs_[64], nm_[64];
    int y = blockIdx.x, b = blockIdx.y, x = threadIdx.x;
    for (int i = threadIdx.x; i < 576; i += 256) w[i] = wp[i];
    if (threadIdx.x < 64) {
        float2 s = *(const float2*)&st[(b*64 + threadIdx.x)*2];
        float m = s.x*(1.f/65536.f);
        float r = rsqrtf(fmaxf(s.y*(1.f/65536.f) - m*m, 0.f) + EPSN);
        rs_[threadIdx.x] = r; nm_[threadIdx.x] = -m*r;
    }
    __syncthreads();
    int ry[3] = { max(y-1,0)*WW, y*WW, min(y+1,HH-1)*WW };
    int cx[3] = { max(x-1,0), x, min(x+1,WW-1) };
    float acc = 0.f;
    for (int ic = 0; ic < 64; ic++) {
        const float* ip = in + (size_t)(b*64 + ic)*PLANE;
        float r = rs_[ic], n = nm_[ic];
        #pragma unroll
        for (int kr = 0; kr < 3; kr++)
            #pragma unroll
            for (int kc = 0; kc < 3; kc++) {
                float v = fmaf(ip[ry[kr] + cx[kc]], r, n);
                v = (v >= 0.f) ? v : SLOPE*v;
                acc = fmaf(v, w[ic*9 + kr*3 + kc], acc);
            }
    }
    float v = acc + bp[0] + xIn[(size_t)b*PLANE + y*WW + x];
    hr[(size_t)b*PLANE + y*WW + x] = v;
    if (write_dout) dout[(size_t)b*PLANE + y*WW + x] = v;
}

// ---------------- loss ----------------
__global__ void __launch_bounds__(256) loss_partial_kernel(
    const float* __restrict__ hr, const float* __restrict__ target) {
    const int off = blockIdx.x, b = blockIdx.y;
    const int dy = off / 13, dx = off - dy*13;
    const float* hp = hr + (size_t)b*PLANE;
    const float* tp = target + (size_t)b*PLANE;
    float s = 0.f, s2 = 0.f;
    for (int i = threadIdx.x; i < NCROP; i += 256) {
        int r = i / CROP, c = i - r*CROP;
        float d = hp[(dy + r)*WW + (dx + c)] - tp[(6 + r)*WW + (6 + c)];
        s += d; s2 = fmaf(d, d, s2);
    }
    __shared__ float sh[2][8];
    int lane = threadIdx.x & 31, w = threadIdx.x >> 5;
    #pragma unroll
    for (int d = 16; d > 0; d >>= 1) {
        s  += __shfl_down_sync(~0u, s, d);
        s2 += __shfl_down_sync(~0u, s2, d);
    }
    if (lane == 0) { sh[0][w] = s; sh[1][w] = s2; }
    __syncthreads();
    if (threadIdx.x == 0) {
        float S = 0.f, S2 = 0.f;
        #pragma unroll
        for (int i = 0; i < 8; i++) { S += sh[0][i]; S2 += sh[1][i]; }
        float m = S / (float)NCROP;
        g_loss[off*BB + b] = S2 / (float)NCROP - m*m;
    }
}

__global__ void loss_final_kernel(float* __restrict__ dout, int out_size) {
    __shared__ float mins[8];
    int w = threadIdx.x >> 5, lane = threadIdx.x & 31;
    if (w < 8) {
        float mn = 3.4e38f;
        for (int off = lane; off < NOFF; off += 32)
            mn = fminf(mn, g_loss[off*BB + w]);
        #pragma unroll
        for (int d = 16; d > 0; d >>= 1)
            mn = fminf(mn, __shfl_down_sync(~0u, mn, d));
        if (lane == 0) mins[w] = mn;
    }
    __syncthreads();
    if (threadIdx.x == 0) {
        float s = 0.f;
        #pragma unroll
        for (int i = 0; i < 8; i++) s += mins[i];
        dout[out_size - 1] = s * (1.f/8.f);
    }
}

// ---------------- launcher ----------------
extern "C" void kernel_launch(void* const* d_in, const int* in_sizes, int n_in,
                              void* d_out, int out_size) {
    const float* xIn    = (const float*)d_in[0];
    const float* target = (const float*)d_in[1];
    const float* w0     = (const float*)d_in[2];
    const float* ws     = (const float*)d_in[4];
    const float* wp     = (const float*)d_in[6];
    const float* bp     = (const float*)d_in[7];
    float* outp = (float*)d_out;

    float *bufA, *bufB, *stats, *hr;
    cudaGetSymbolAddress((void**)&bufA,  g_bufA);
    cudaGetSymbolAddress((void**)&bufB,  g_bufB);
    cudaGetSymbolAddress((void**)&stats, g_stats);
    cudaGetSymbolAddress((void**)&hr,    g_hr);

    cudaFuncSetAttribute(tconv_kernel, cudaFuncAttributeMaxDynamicSharedMemorySize, TSM);

    zero_stats_kernel<<<32, 256>>>();
    wprep_kernel<<<1008, 256>>>(ws);
    conv0_kernel<<<dim3(HH, BB), 256>>>(xIn, w0, bufA);
    stats_kernel<<<BB*CC, 256>>>(bufA, stats);

    float* cur = bufA; float* nxt = bufB;
    for (int l = 1; l <= 7; l++) {
        tconv_kernel<<<dim3(2, HH, BB), 256, TSM>>>(
            cur, stats + (l-1)*BB*CC*2, nxt, stats + l*BB*CC*2, l - 1);
        float* tmp = cur; cur = nxt; nxt = tmp;
    }

    int write_dout = (out_size >= BB*PLANE + 1) ? 1 : 0;
    proj_kernel<<<dim3(HH, BB), 256>>>(
        cur, stats + 7*BB*CC*2, wp, bp, xIn, hr, outp, write_dout);
    loss_partial_kernel<<<dim3(NOFF, BB), 256>>>(hr, target);
    loss_final_kernel<<<1, 256>>>(outp, out_size);
}